// round 5
// baseline (speedup 1.0000x reference)
#include <cuda_runtime.h>

// Problem constants
#define CC   64          // channels (CIN == COUT)
#define SS   128         // H == W
#define P    16384       // SS*SS pixels
#define NB   2           // batch

// ---------------- device scratch (static __device__, no allocations) ----------------
__device__ float  g_Q   [NB*CC*P];
__device__ float  g_Kc  [NB*CC*P];
__device__ float  g_Vc  [NB*CC*P];
__device__ float  g_out [NB*CC*P];
__device__ float2 g_F   [NB*P];
__device__ float2 g_bufA[NB*CC*P];   // FFT ping buffer
__device__ float2 g_outft[NB*CC*P];  // frequency-domain product
__device__ float  g_out1[NB*CC*P];   // spectral branch spatial result
__device__ float  g_M   [CC*CC];
__device__ float  g_bias[CC];
__device__ float  g_part[256];

// ---------------- kernel 1: collapse conv chain to M, bias ----------------
__global__ void precompute_M(const float* __restrict__ w0,  const float* __restrict__ w0b,
                             const float* __restrict__ cv,  const float* __restrict__ cvb,
                             const float* __restrict__ cv1, const float* __restrict__ cv1b) {
    __shared__ float T[CC*CC];
    __shared__ float tb[CC];
    int tid = threadIdx.x;
    for (int idx = tid; idx < CC*CC; idx += 256) {
        int o = idx >> 6, c = idx & 63;
        float s = 0.f;
        #pragma unroll 8
        for (int k = 0; k < CC; k++) s += w0[o*CC + k] * cv[k*CC + c];
        T[idx] = s;
    }
    if (tid < CC) {
        float s = 0.f;
        for (int j = 0; j < CC; j++) s += w0[tid*CC + j] * cvb[j];
        tb[tid] = s + w0b[tid];
    }
    __syncthreads();
    for (int idx = tid; idx < CC*CC; idx += 256) {
        int o = idx >> 6, c = idx & 63;
        float s = 0.f;
        #pragma unroll 8
        for (int k = 0; k < CC; k++) s += cv1[o*CC + k] * T[k*CC + c];
        g_M[idx] = s;
    }
    if (tid < CC) {
        float s = 0.f;
        for (int k = 0; k < CC; k++) s += cv1[tid*CC + k] * tb[k];
        g_bias[tid] = s + cv1b[tid];
    }
}

// ---------------- kernel 2: Q/K/V 1x1 convs (tiled SGEMM) ----------------
// grid (128 pixel-tiles, NB), block 256, dyn smem 81920
__global__ void qkv_kernel(const float* __restrict__ fs,
                           const float* __restrict__ wq,
                           const float* __restrict__ wk,
                           const float* __restrict__ wv) {
    extern __shared__ float sm[];
    float* sw = sm;            // 3 * 64 * 64 (transposed: [m][k][o])
    float* sf = sm + 12288;    // 64 * 128
    int tid = threadIdx.x;
    int b   = blockIdx.y;
    int p0  = blockIdx.x * 128;

    const float* wmats[3] = {wq, wk, wv};
    #pragma unroll
    for (int m = 0; m < 3; m++) {
        const float* w = wmats[m];
        for (int idx = tid; idx < 4096; idx += 256) {
            int o = idx >> 6, k = idx & 63;
            sw[m*4096 + k*64 + o] = w[idx];  // w[o][k] -> sw[k][o]
        }
    }
    for (int idx = tid; idx < 8192; idx += 256) {
        int c = idx >> 7, pp = idx & 127;
        sf[c*128 + pp] = fs[((b*CC + c) << 14) + p0 + pp];
    }
    __syncthreads();

    int c0  = (tid >> 4) * 4;
    int pp0 = (tid & 15) * 8;

    #pragma unroll
    for (int m = 0; m < 3; m++) {
        float acc[4][8];
        #pragma unroll
        for (int i = 0; i < 4; i++)
            #pragma unroll
            for (int j = 0; j < 8; j++) acc[i][j] = 0.f;

        #pragma unroll 4
        for (int k = 0; k < 64; k++) {
            float4 w4 = *reinterpret_cast<const float4*>(&sw[m*4096 + k*64 + c0]);
            float4 fa = *reinterpret_cast<const float4*>(&sf[k*128 + pp0]);
            float4 fb = *reinterpret_cast<const float4*>(&sf[k*128 + pp0 + 4]);
            float wv4[4] = {w4.x, w4.y, w4.z, w4.w};
            float fv[8]  = {fa.x, fa.y, fa.z, fa.w, fb.x, fb.y, fb.z, fb.w};
            #pragma unroll
            for (int i = 0; i < 4; i++)
                #pragma unroll
                for (int j = 0; j < 8; j++)
                    acc[i][j] += wv4[i] * fv[j];
        }
        float* dst = (m == 0) ? g_Q : ((m == 1) ? g_Kc : g_Vc);
        #pragma unroll
        for (int i = 0; i < 4; i++) {
            float* dp = dst + ((b*CC + c0 + i) << 14) + p0 + pp0;
            *reinterpret_cast<float4*>(dp)     = make_float4(acc[i][0], acc[i][1], acc[i][2], acc[i][3]);
            *reinterpret_cast<float4*>(dp + 4) = make_float4(acc[i][4], acc[i][5], acc[i][6], acc[i][7]);
        }
    }
}

// ---------------- kernel 3: 9-tap per-channel softmax attention ----------------
// grid 8192, block 256
__global__ void attn_kernel(const float* __restrict__ relh,
                            const float* __restrict__ relw) {
    int idx = blockIdx.x * 256 + threadIdx.x;   // = (b*64+c)*P + p
    int p  = idx & (P - 1);
    int bc = idx >> 14;
    int c  = bc & 63;
    int h  = p >> 7, w = p & 127;

    float q = g_Q[idx];
    float bias[9];
    if (c < 32) {
        float b0 = relh[c*3 + 0], b1 = relh[c*3 + 1], b2 = relh[c*3 + 2];
        bias[0] = bias[1] = bias[2] = b0;
        bias[3] = bias[4] = bias[5] = b1;
        bias[6] = bias[7] = bias[8] = b2;
    } else {
        float b0 = relw[(c-32)*3 + 0], b1 = relw[(c-32)*3 + 1], b2 = relw[(c-32)*3 + 2];
        bias[0] = bias[3] = bias[6] = b0;
        bias[1] = bias[4] = bias[7] = b1;
        bias[2] = bias[5] = bias[8] = b2;
    }
    const float* Kb = g_Kc + (bc << 14);
    const float* Vb = g_Vc + (bc << 14);

    float l[9], v[9];
    float mx = -1e30f;
    #pragma unroll
    for (int t = 0; t < 9; t++) {
        int dh = t / 3 - 1, dw = t % 3 - 1;
        int h2 = h + dh, w2 = w + dw;
        bool in = ((unsigned)h2 < 128u) && ((unsigned)w2 < 128u);
        float kk = in ? Kb[h2*128 + w2] : 0.f;
        float vv = in ? Vb[h2*128 + w2] : 0.f;
        kk += bias[t];
        l[t] = q * kk;
        v[t] = vv;
        mx = fmaxf(mx, l[t]);
    }
    float se = 0.f, acc = 0.f;
    #pragma unroll
    for (int t = 0; t < 9; t++) {
        float e = __expf(l[t] - mx);
        se  += e;
        acc += e * v[t];
    }
    g_out[idx] = acc / se;
}

// ---------------- FFT pass: warp-per-row 128-pt radix-2, transposed store ----------------
// MODE 0: fwd pass1  (real in: g_out ch32) -> g_bufA          sign -1, scale 1
// MODE 1: fwd pass2  (g_bufA) -> g_F                          sign -1, scale 1/128
// MODE 2: inv pass1  (g_outft) -> g_bufA                      sign +1, scale 1
// MODE 3: inv pass2  (g_bufA) -> g_out1 (real out)            sign +1, scale 1/128
template<int MODE>
__global__ void fft_pass() {
    __shared__ float2 S[8][128];
    int t    = blockIdx.x >> 4;
    int rb   = blockIdx.x & 15;
    int wid  = threadIdx.x >> 5;
    int lane = threadIdx.x & 31;
    int a    = rb * 8 + wid;

    const float sign  = (MODE < 2) ? -1.f : 1.f;
    const float scale = (MODE == 1 || MODE == 3) ? (1.f/128.f) : 1.f;

    if (MODE == 0) {
        const float* p = g_out + 32*P + (long)t*(CC*P) + a*128;
        #pragma unroll
        for (int e = 0; e < 4; e++) {
            int j = lane + e*32;
            int r = __brev((unsigned)j) >> 25;
            S[wid][r] = make_float2(p[j], 0.f);
        }
    } else {
        const float2* p = ((MODE == 2) ? g_outft : g_bufA) + (long)t*P + a*128;
        #pragma unroll
        for (int e = 0; e < 4; e++) {
            int j = lane + e*32;
            int r = __brev((unsigned)j) >> 25;
            S[wid][r] = p[j];
        }
    }

    #pragma unroll
    for (int s = 1; s <= 7; s++) {
        int half = 1 << (s - 1);
        __syncwarp();
        #pragma unroll
        for (int e = 0; e < 2; e++) {
            int bf = lane + e*32;          // 0..63
            int j  = bf & (half - 1);
            int g  = bf >> (s - 1);
            int i0 = (g << s) + j;
            int i1 = i0 + half;
            float ang = sign * (6.28318530717958647692f / (float)(2*half)) * (float)j;
            float cs, sn;
            sincosf(ang, &cs, &sn);
            float2 u  = S[wid][i0];
            float2 vv = S[wid][i1];
            float2 wv = make_float2(cs*vv.x - sn*vv.y, cs*vv.y + sn*vv.x);
            S[wid][i0] = make_float2(u.x + wv.x, u.y + wv.y);
            S[wid][i1] = make_float2(u.x - wv.x, u.y - wv.y);
        }
    }
    __syncthreads();

    #pragma unroll
    for (int it = 0; it < 4; it++) {
        int el = it*256 + threadIdx.x;
        int j  = el >> 3, aa = el & 7;
        float2 v = S[aa][j];
        long off = (long)t*P + (long)j*128 + rb*8 + aa;   // transposed
        if (MODE == 0)      g_bufA[off] = v;
        else if (MODE == 1) g_F[off]    = make_float2(v.x*scale, v.y*scale);
        else if (MODE == 2) g_bufA[off] = v;
        else                g_out1[off] = v.x * scale;
    }
}

// ---------------- kernel 5: fused weights1 reduction + freq multiply (HBM bound) ----------------
// grid (16, 64), block 256
__global__ void wmul_kernel(const float* __restrict__ wr, const float* __restrict__ wi) {
    int c  = blockIdx.y;
    int t4 = blockIdx.x * 256 + threadIdx.x;       // float4 index in [0,4096)
    const float4* pr = reinterpret_cast<const float4*>(wr + (long)c*CC*P) + t4;
    const float4* pi = reinterpret_cast<const float4*>(wi + (long)c*CC*P) + t4;

    float4 ar = make_float4(0,0,0,0), ai = make_float4(0,0,0,0);
    #pragma unroll 8
    for (int i = 0; i < 64; i++) {
        float4 r = pr[i*4096];
        float4 m = pi[i*4096];
        ar.x += r.x; ar.y += r.y; ar.z += r.z; ar.w += r.w;
        ai.x += m.x; ai.y += m.y; ai.z += m.z; ai.w += m.w;
    }
    int uv0 = t4 * 4;
    float sr[4] = {ar.x, ar.y, ar.z, ar.w};
    float si[4] = {ai.x, ai.y, ai.z, ai.w};
    #pragma unroll
    for (int b = 0; b < 2; b++) {
        const float2* Fp = g_F + b*P + uv0;
        float2* op = g_outft + ((b*CC + c) << 14) + uv0;
        #pragma unroll
        for (int e = 0; e < 4; e++) {
            float2 F = Fp[e];
            op[e] = make_float2(sr[e]*F.x - si[e]*F.y, sr[e]*F.y + si[e]*F.x);
        }
    }
}

// ---------------- kernel 6: out2 = M@out + bias, combine, squared error ----------------
// grid 256 (= NB * 128 tiles), block 256, dyn smem 82432
__global__ void final_kernel(const float* __restrict__ ft,
                             const float* __restrict__ rate1,
                             const float* __restrict__ rate2) {
    extern __shared__ float sm[];
    float* sOut = sm;            // 64 * 128 = 8192
    float* sFt  = sm + 8192;     // 128 * 65 = 8320 (padded)
    float* sMT  = sm + 16512;    // 64 * 64  = 4096 (transposed [k][o])
    int tid = threadIdx.x;
    int b   = blockIdx.x >> 7;
    int p0  = (blockIdx.x & 127) * 128;

    for (int idx = tid; idx < 8192; idx += 256) {
        int c = idx >> 7, pp = idx & 127;
        sOut[idx] = g_out[((b*CC + c) << 14) + p0 + pp];
    }
    for (int idx = tid; idx < 8192; idx += 256) {
        int pp = idx >> 6, c = idx & 63;
        sFt[pp*65 + c] = ft[((long)(b*P + p0 + pp))*64 + c];
    }
    for (int idx = tid; idx < 4096; idx += 256) {
        int o = idx >> 6, k = idx & 63;
        sMT[k*64 + o] = g_M[idx];
    }
    __syncthreads();

    int c0  = (tid >> 4) * 4;
    int pp0 = (tid & 15) * 8;

    float acc[4][8];
    #pragma unroll
    for (int i = 0; i < 4; i++) {
        float bb = g_bias[c0 + i];
        #pragma unroll
        for (int j = 0; j < 8; j++) acc[i][j] = bb;
    }
    #pragma unroll 4
    for (int k = 0; k < 64; k++) {
        float4 m4 = *reinterpret_cast<const float4*>(&sMT[k*64 + c0]);
        float4 fa = *reinterpret_cast<const float4*>(&sOut[k*128 + pp0]);
        float4 fb = *reinterpret_cast<const float4*>(&sOut[k*128 + pp0 + 4]);
        float mv[4] = {m4.x, m4.y, m4.z, m4.w};
        float fv[8] = {fa.x, fa.y, fa.z, fa.w, fb.x, fb.y, fb.z, fb.w};
        #pragma unroll
        for (int i = 0; i < 4; i++)
            #pragma unroll
            for (int j = 0; j < 8; j++)
                acc[i][j] += mv[i] * fv[j];
    }

    float r1 = rate1[0], r2 = rate2[0];
    float local = 0.f;
    #pragma unroll
    for (int i = 0; i < 4; i++) {
        int c = c0 + i;
        const float* o1p = g_out1 + ((b*CC + c) << 14) + p0 + pp0;
        #pragma unroll
        for (int j = 0; j < 8; j++) {
            float val = r1 * o1p[j] + r2 * acc[i][j] - sFt[(pp0 + j)*65 + c];
            local += val * val;
        }
    }
    __syncthreads();
    sOut[tid] = local;
    __syncthreads();
    for (int s = 128; s > 0; s >>= 1) {
        if (tid < s) sOut[tid] += sOut[tid + s];
        __syncthreads();
    }
    if (tid == 0) g_part[blockIdx.x] = sOut[0];
}

__global__ void reduce_kernel(float* __restrict__ out) {
    __shared__ float s[256];
    s[threadIdx.x] = g_part[threadIdx.x];
    __syncthreads();
    for (int st = 128; st > 0; st >>= 1) {
        if (threadIdx.x < st) s[threadIdx.x] += s[threadIdx.x + st];
        __syncthreads();
    }
    if (threadIdx.x == 0) out[0] = s[0] / 2097152.0f;  // mean over 2*64*128*128
}

// ---------------- host ----------------
extern "C" void kernel_launch(void* const* d_in, const int* in_sizes, int n_in,
                              void* d_out, int out_size) {
    const float* fs    = (const float*)d_in[0];
    const float* ft    = (const float*)d_in[1];
    const float* w_q   = (const float*)d_in[2];
    const float* w_k   = (const float*)d_in[3];
    const float* w_v   = (const float*)d_in[4];
    const float* rel_h = (const float*)d_in[5];
    const float* rel_w = (const float*)d_in[6];
    const float* w1r   = (const float*)d_in[7];
    const float* w1i   = (const float*)d_in[8];
    const float* w0w   = (const float*)d_in[9];
    const float* w0b   = (const float*)d_in[10];
    const float* cvw   = (const float*)d_in[11];
    const float* cvb   = (const float*)d_in[12];
    const float* cv1w  = (const float*)d_in[13];
    const float* cv1b  = (const float*)d_in[14];
    const float* rate1 = (const float*)d_in[15];
    const float* rate2 = (const float*)d_in[16];

    cudaFuncSetAttribute(qkv_kernel,   cudaFuncAttributeMaxDynamicSharedMemorySize, 81920);
    cudaFuncSetAttribute(final_kernel, cudaFuncAttributeMaxDynamicSharedMemorySize, 82432);

    precompute_M<<<1, 256>>>(w0w, w0b, cvw, cvb, cv1w, cv1b);
    qkv_kernel<<<dim3(128, 2), 256, 81920>>>(fs, w_q, w_k, w_v);
    attn_kernel<<<8192, 256>>>(rel_h, rel_w);
    fft_pass<0><<<32, 256>>>();     // fwd rows (2 transforms)
    fft_pass<1><<<32, 256>>>();     // fwd cols -> g_F
    wmul_kernel<<<dim3(16, 64), 256>>>(w1r, w1i);   // 512 MiB stream — the HBM floor
    fft_pass<2><<<2048, 256>>>();   // inv pass1 (128 transforms)
    fft_pass<3><<<2048, 256>>>();   // inv pass2 -> g_out1 (real)
    final_kernel<<<256, 256, 82432>>>(ft, rate1, rate2);
    reduce_kernel<<<1, 256>>>((float*)d_out);
}